// round 15
// baseline (speedup 1.0000x reference)
#include <cuda_runtime.h>
#include <cuda_fp16.h>

#define N_NODES 100000
#define N_EDGES 1600000
#define NB_SCAN 98              // ceil((N_NODES+1)/1024)
#define NEG_SLOPE 0.2f
#define FULLM 0xffffffffu
#define GB_G1 782               // ceil(N_NODES/128) gemm tiles
#define GB_HIST 6250            // ceil(N_EDGES/256)
#define GB_FILL 782             // ceil(N_EDGES/2048): 4 edges per thread
#define GB_AGG 3125

// ---------------- scratch (device globals; zero-initialized at module load) ----------
// Cross-call invariant: g_deg, g_tstat, g_done are zero at the start of every
// kernel_launch call — module-load zero-init covers the first call; k_fill /
// agg2's last block re-zero them for every later call. g_m is zeroed by
// k_fill each call before agg2 accumulates into it.
__device__ int      g_deg[N_NODES + 1];
__device__ int      g_rowptr[N_NODES + 1];
__device__ int      g_ord[N_EDGES];       // within-dst-bucket rank of each edge
__device__ unsigned g_tstat[NB_SCAN];     // lookback status: [31:30] flag (1=agg,2=prefix), [29:0] value
__device__ int      g_adj[N_EDGES];       // src indices in CSR (dst-grouped) order
__device__ uint2    g_h[N_NODES * 16];    // layer-1 features, fp16 rows (64 x half = 128B/row)
__device__ uint2    g_feat[N_NODES * 16]; // layer-1 output, fp16 rows (layer-2 gather source)
__device__ float    g_as[N_NODES];        // layer-1 logit halves (fp32)
__device__ float    g_ad[N_NODES];
__device__ float    g_as2[N_NODES];       // layer-2 logit halves (feat . u / feat . v)
__device__ float    g_ad2[N_NODES];
__device__ float    g_u[64];              // u = W2^T a_src2
__device__ float    g_v[64];              // v = W2^T a_dst2
__device__ float    g_m[64];              // softmax-weighted feat aggregate (sum over nodes)
__device__ int      g_done;               // agg2 completed-block counter (last block runs fin)

__device__ __forceinline__ uint2 pack4h(float a, float b, float c, float d) {
    __half2 p0 = __floats2half2_rn(a, b);
    __half2 p1 = __floats2half2_rn(c, d);
    uint2 r;
    r.x = *reinterpret_cast<unsigned*>(&p0);
    r.y = *reinterpret_cast<unsigned*>(&p1);
    return r;
}
__device__ __forceinline__ unsigned tf32b(float f) {
    unsigned r;
    asm("cvt.rna.tf32.f32 %0, %1;" : "=r"(r) : "f"(f));
    return r;
}
__device__ __forceinline__ unsigned packh2(float a, float b) {
    __half2 p = __floats2half2_rn(a, b);
    return *reinterpret_cast<unsigned*>(&p);
}
__device__ __forceinline__ __half2 u2h2(unsigned u) {
    return *reinterpret_cast<__half2*>(&u);
}

// ---------------- tf32 mma.sync GEMM (h = X @ W1^T) + attention logits ---------------
// Block = 256 threads = 8 warps; tile 128 nodes x 64 outs. Warp w owns rows
// w*16..+15; per warp 8 n-blocks of m16n8k8 tf32 mma (fp32 accumulate).
// K staged 16 at a time into smem (tf32-converted), row stride 20 words:
// all A/B fragment LDS patterns are bank-conflict-free. Logits reduced
// in-warp over the 4 quad threads. h written as fp16 rows (agg layout).
// HIST blocks (>= GB_G1) run the dst-degree histogram + bucket-rank capture;
// the atomicAdd return value IS the edge's rank -> k_fill needs no atomics.
__global__ void __launch_bounds__(256)
k_gemm1(const float* __restrict__ X,
        const float* __restrict__ W,
        const float* __restrict__ avsrc,
        const float* __restrict__ avdst,
        const int* __restrict__ ei) {
    if (blockIdx.x >= GB_G1) {
        int e = (blockIdx.x - GB_G1) * 256 + threadIdx.x;
        if (e < N_EDGES) {
            int d = __ldg(&ei[N_EDGES + e]);
            g_ord[e] = atomicAdd(&g_deg[d + 1], 1);
        }
        return;
    }
    __shared__ unsigned xs[128][20];   // X chunk, tf32 bits, [row][k0..15], stride 20
    __shared__ unsigned ws[64][20];    // W chunk, tf32 bits, [out][k0..15]

    const int tid  = threadIdx.x;
    const int lane = tid & 31;
    const int wid  = tid >> 5;         // warp 0..7
    const int g    = lane >> 2;        // groupID (row-in-16 / col-in-8)
    const int tg   = lane & 3;         // threadID_in_group
    const int nbase = blockIdx.x * 128;
    const int m0 = wid * 16;

    const float4* X4 = (const float4*)X;   // 32 float4 per 128-float row
    const float4* W4 = (const float4*)W;

    float acc[8][4];
#pragma unroll
    for (int nb = 0; nb < 8; nb++)
#pragma unroll
        for (int i = 0; i < 4; i++) acc[nb][i] = 0.f;

#pragma unroll 1
    for (int ch = 0; ch < 8; ch++) {
        __syncthreads();
        // stage X chunk: 128 rows x 16 k (512 float4, 2 per thread)
#pragma unroll
        for (int it = 0; it < 2; it++) {
            int idx = tid + it * 256;
            int r  = idx >> 2;
            int c4 = idx & 3;
            int xrow = min(nbase + r, N_NODES - 1);        // clamp tail (stores guarded)
            float4 v = __ldg(&X4[(long)xrow * 32 + ch * 4 + c4]);
            *(uint4*)&xs[r][c4 * 4] =
                make_uint4(tf32b(v.x), tf32b(v.y), tf32b(v.z), tf32b(v.w));
        }
        // stage W chunk: 64 rows x 16 k (256 float4, 1 per thread)
        {
            int r  = tid >> 2;
            int c4 = tid & 3;
            float4 v = __ldg(&W4[(long)r * 32 + ch * 4 + c4]);
            *(uint4*)&ws[r][c4 * 4] =
                make_uint4(tf32b(v.x), tf32b(v.y), tf32b(v.z), tf32b(v.w));
        }
        __syncthreads();

#pragma unroll
        for (int ks = 0; ks < 2; ks++) {
            const int kb = ks * 8;
            unsigned a0 = xs[m0 + g][kb + tg];
            unsigned a1 = xs[m0 + g + 8][kb + tg];
            unsigned a2 = xs[m0 + g][kb + tg + 4];
            unsigned a3 = xs[m0 + g + 8][kb + tg + 4];
#pragma unroll
            for (int nb = 0; nb < 8; nb++) {
                unsigned b0 = ws[nb * 8 + g][kb + tg];
                unsigned b1 = ws[nb * 8 + g][kb + tg + 4];
                asm volatile(
                    "mma.sync.aligned.m16n8k8.row.col.f32.tf32.tf32.f32 "
                    "{%0,%1,%2,%3}, {%4,%5,%6,%7}, {%8,%9}, {%0,%1,%2,%3};"
                    : "+f"(acc[nb][0]), "+f"(acc[nb][1]),
                      "+f"(acc[nb][2]), "+f"(acc[nb][3])
                    : "r"(a0), "r"(a1), "r"(a2), "r"(a3), "r"(b0), "r"(b1));
            }
        }
    }

    // epilogue: thread holds rows node0/node1, cols {nb*8 + tg*2, +1}
    const int node0 = nbase + m0 + g;
    const int node1 = node0 + 8;
    unsigned* H2 = (unsigned*)g_h;     // half2 words, 32 per node row

    float sp0 = 0.f, dp0 = 0.f, sp1 = 0.f, dp1 = 0.f;
    const float2* AS2 = (const float2*)avsrc;
    const float2* AD2 = (const float2*)avdst;
#pragma unroll
    for (int nb = 0; nb < 8; nb++) {
        float2 sv = __ldg(&AS2[nb * 4 + tg]);
        float2 dv = __ldg(&AD2[nb * 4 + tg]);
        sp0 += acc[nb][0] * sv.x + acc[nb][1] * sv.y;
        dp0 += acc[nb][0] * dv.x + acc[nb][1] * dv.y;
        sp1 += acc[nb][2] * sv.x + acc[nb][3] * sv.y;
        dp1 += acc[nb][2] * dv.x + acc[nb][3] * dv.y;
        if (node0 < N_NODES)
            H2[(long)node0 * 32 + nb * 4 + tg] = packh2(acc[nb][0], acc[nb][1]);
        if (node1 < N_NODES)
            H2[(long)node1 * 32 + nb * 4 + tg] = packh2(acc[nb][2], acc[nb][3]);
    }
    // reduce over the 4 quad threads sharing a row
#pragma unroll
    for (int m = 1; m < 4; m <<= 1) {
        sp0 += __shfl_xor_sync(FULLM, sp0, m);
        dp0 += __shfl_xor_sync(FULLM, dp0, m);
        sp1 += __shfl_xor_sync(FULLM, sp1, m);
        dp1 += __shfl_xor_sync(FULLM, dp1, m);
    }
    if (tg == 0) {
        if (node0 < N_NODES) { g_as[node0] = sp0; g_ad[node0] = dp0; }
        if (node1 < N_NODES) { g_as[node1] = sp1; g_ad[node1] = dp1; }
    }
}

// ---------------- single-kernel decoupled-lookback scan of g_deg -> g_rowptr ----------
__global__ void __launch_bounds__(1024) k_scan() {
    __shared__ int s[1024];
    __shared__ int s_prefix;
    const int t = threadIdx.x;
    const int tile = blockIdx.x;
    const int i = tile * 1024 + t;
    int v = (i <= N_NODES) ? g_deg[i] : 0;
    s[t] = v;
    __syncthreads();
    for (int off = 1; off < 1024; off <<= 1) {
        int x = (t >= off) ? s[t - off] : 0;
        __syncthreads();
        s[t] += x;
        __syncthreads();
    }
    const int inc = s[t];
    const int total = s[1023];

    if (t == 0) {
        if (tile == 0) {
            atomicExch(&g_tstat[0], (2u << 30) | (unsigned)total);
            s_prefix = 0;
        } else {
            atomicExch(&g_tstat[tile], (1u << 30) | (unsigned)total);
            int prefix = 0;
            int p = tile - 1;
            while (true) {
                unsigned st = *(volatile unsigned*)&g_tstat[p];
                unsigned f = st >> 30;
                if (f == 0u) continue;
                prefix += (int)(st & 0x3FFFFFFFu);
                if (f == 2u) break;
                p--;
            }
            atomicExch(&g_tstat[tile], (2u << 30) | (unsigned)(prefix + total));
            s_prefix = prefix;
        }
    }
    __syncthreads();
    const int val = inc + s_prefix;
    if (i <= N_NODES) g_rowptr[i] = val;
}

// ---------------- atomic-free adjacency fill (4 edges/thread) + u/v + cleanup -------
// pos = rowptr[dst] + precomputed bucket rank: loads + one scattered store.
// 4 edges per thread -> 4 independent ld.dst -> ld.rowptr -> st chains in
// flight (the 1-edge version was MLP-1 latency-bound: issue 8%).
// Block GB_FILL computes u = W2^T a_src2, v = W2^T a_dst2 and zeroes g_m.
__global__ void __launch_bounds__(512) k_fill(const int* __restrict__ ei,
                                              const float* __restrict__ W2,
                                              const float* __restrict__ as2v,
                                              const float* __restrict__ ad2v) {
    if (blockIdx.x == GB_FILL) {
        int k = threadIdx.x;
        if (k < 64) {
            float u = 0.f, v = 0.f;
#pragma unroll 8
            for (int o = 0; o < 64; o++) {
                float w = __ldg(&W2[o * 64 + k]);
                u += __ldg(&as2v[o]) * w;
                v += __ldg(&ad2v[o]) * w;
            }
            g_u[k] = u;
            g_v[k] = v;
            g_m[k] = 0.f;
        }
        return;
    }
    // scratch reset for the next kernel_launch call (flat index over 782x512)
    int rid = blockIdx.x * 512 + threadIdx.x;
    for (int r = rid; r <= N_NODES; r += GB_FILL * 512) g_deg[r] = 0;
    if (rid < NB_SCAN) g_tstat[rid] = 0u;

    const int ebase = blockIdx.x * 2048 + threadIdx.x;
    int d[4], pos[4], srcv[4];
#pragma unroll
    for (int i = 0; i < 4; i++) {
        int e = ebase + i * 512;
        if (e < N_EDGES) {
            d[i]    = __ldg(&ei[N_EDGES + e]);
            srcv[i] = __ldg(&ei[e]);
        } else d[i] = -1;
    }
#pragma unroll
    for (int i = 0; i < 4; i++)
        if (d[i] >= 0) pos[i] = __ldg(&g_rowptr[d[i]]) + __ldg(&g_ord[ebase + i * 512]);
#pragma unroll
    for (int i = 0; i < 4; i++)
        if (d[i] >= 0) g_adj[pos[i]] = srcv[i];
}

// ---------------- half-warp-per-node softmax aggregation (atomic-free) ---------------
// 16 lanes own one node; lane l holds features [4l, 4l+4) as fp16 (8B/lane):
// one 128B wavefront per gathered edge row. Accumulation in fp16 via HFMA2 —
// the per-chunk edge weight is converted once per lane to a broadcast half2
// (scaled by 1/16, exact in fp16, restored x16 in fp32 after the loop) and
// shfl'd as raw bits. dsum, softmax normalize, logits, bias all stay fp32.
// Single predicated 4-wide batch loop: invalid tail slots carry (s=0, exh=0)
// so they gather row 0 with zero weight.
// mode 1: bias+relu, store g_feat (fp16) + emit layer-2 logit halves
//         as2 = feat.u, ad2 = feat.v (replaces the layer-2 gemm by linearity).
// mode 2: pool normalized aggregate into g_m; the LAST completed block folds
//         the final projection out = W2 (g_m/N) + b2 (threadfence + counter).
__global__ void __launch_bounds__(512)
k_agg(const float* __restrict__ b, const float* __restrict__ W2,
      const float* __restrict__ b2, float* __restrict__ out, int mode) {
    __shared__ float sred[64];
    __shared__ int islast;
    if (mode == 2) {
        if (threadIdx.x < 64) sred[threadIdx.x] = 0.f;
        __syncthreads();
    }
    const int lane = threadIdx.x & 31;
    const int l = lane & 15;
    const unsigned hm = 0xFFFFu << (lane & 16);
    const int node = (blockIdx.x * 512 + threadIdx.x) >> 4;   // exact: 3125*512/16 = 100000

    const uint2* H = (mode == 1) ? g_h : g_feat;
    const float* asp = (mode == 1) ? g_as : g_as2;
    const float* adp = (mode == 1) ? g_ad : g_ad2;

    const float adn = adp[node];
    float e0 = asp[node] + adn;
    e0 = (e0 > 0.f) ? e0 : NEG_SLOPE * e0;
    const float exs = __expf(e0);                 // self-loop term (fp32 for denom)

    uint2 hrow = __ldg(H + (long)node * 16 + l);
    __half2 es2 = __float2half2_rn(exs * 0.0625f);
    __half2 hacc0 = __hmul2(es2, u2h2(hrow.x));
    __half2 hacc1 = __hmul2(es2, u2h2(hrow.y));
    float dsum = 0.f;

    const int beg = __ldg(&g_rowptr[node]);
    const int end = __ldg(&g_rowptr[node + 1]);
    for (int k = beg; k < end; k += 16) {
        int idx = k + l;
        int s = 0;
        unsigned exh = 0u;                        // half2(0,0)
        if (idx < end) {
            s = __ldg(&g_adj[idx]);
            float e = __ldg(&asp[s]) + adn;
            e = (e > 0.f) ? e : NEG_SLOPE * e;
            float ex = __expf(e);
            dsum += ex;
            __half2 t = __float2half2_rn(ex * 0.0625f);
            exh = *reinterpret_cast<unsigned*>(&t);
        }
        const int cnt = min(16, end - k);
        for (int j = 0; j < cnt; j += 4) {
            int      s0 = __shfl_sync(hm, s, j, 16);
            int      s1 = __shfl_sync(hm, s, j + 1, 16);
            int      s2 = __shfl_sync(hm, s, j + 2, 16);
            int      s3 = __shfl_sync(hm, s, j + 3, 16);
            unsigned e0b = __shfl_sync(hm, exh, j, 16);
            unsigned e1b = __shfl_sync(hm, exh, j + 1, 16);
            unsigned e2b = __shfl_sync(hm, exh, j + 2, 16);
            unsigned e3b = __shfl_sync(hm, exh, j + 3, 16);
            uint2 h0 = __ldg(H + (long)s0 * 16 + l);
            uint2 h1 = __ldg(H + (long)s1 * 16 + l);
            uint2 h2 = __ldg(H + (long)s2 * 16 + l);
            uint2 h3 = __ldg(H + (long)s3 * 16 + l);
            hacc0 = __hfma2(u2h2(e0b), u2h2(h0.x), hacc0);
            hacc1 = __hfma2(u2h2(e0b), u2h2(h0.y), hacc1);
            hacc0 = __hfma2(u2h2(e1b), u2h2(h1.x), hacc0);
            hacc1 = __hfma2(u2h2(e1b), u2h2(h1.y), hacc1);
            hacc0 = __hfma2(u2h2(e2b), u2h2(h2.x), hacc0);
            hacc1 = __hfma2(u2h2(e2b), u2h2(h2.y), hacc1);
            hacc0 = __hfma2(u2h2(e3b), u2h2(h3.x), hacc0);
            hacc1 = __hfma2(u2h2(e3b), u2h2(h3.y), hacc1);
        }
    }
#pragma unroll
    for (int m = 8; m; m >>= 1) dsum += __shfl_xor_sync(hm, dsum, m, 16);

    // restore scale (x16) and normalize in fp32
    float2 f0 = __half22float2(hacc0);
    float2 f1 = __half22float2(hacc1);
    const float inv = 16.0f / (dsum + exs);
    float4 acc = make_float4(f0.x * inv, f0.y * inv, f1.x * inv, f1.y * inv);

    if (mode == 1) {
        float4 bb = __ldg((const float4*)b + l);
        float4 r = make_float4(fmaxf(acc.x + bb.x, 0.f),
                               fmaxf(acc.y + bb.y, 0.f),
                               fmaxf(acc.z + bb.z, 0.f),
                               fmaxf(acc.w + bb.w, 0.f));
        g_feat[(long)node * 16 + l] = pack4h(r.x, r.y, r.z, r.w);
        // layer-2 logit halves from the in-register (fp32) feat row
        float4 uu = __ldg((const float4*)g_u + l);
        float4 vv = __ldg((const float4*)g_v + l);
        float sp = r.x * uu.x + r.y * uu.y + r.z * uu.z + r.w * uu.w;
        float dp = r.x * vv.x + r.y * vv.y + r.z * vv.z + r.w * vv.w;
#pragma unroll
        for (int m = 8; m; m >>= 1) {
            sp += __shfl_xor_sync(hm, sp, m, 16);
            dp += __shfl_xor_sync(hm, dp, m, 16);
        }
        if (l == 0) { g_as2[node] = sp; g_ad2[node] = dp; }
    } else {
        // pool normalized aggregate into g_m
        __syncwarp(FULLM);
        acc.x += __shfl_xor_sync(FULLM, acc.x, 16);
        acc.y += __shfl_xor_sync(FULLM, acc.y, 16);
        acc.z += __shfl_xor_sync(FULLM, acc.z, 16);
        acc.w += __shfl_xor_sync(FULLM, acc.w, 16);
        if (lane < 16) {
            atomicAdd(&sred[4 * l + 0], acc.x);
            atomicAdd(&sred[4 * l + 1], acc.y);
            atomicAdd(&sred[4 * l + 2], acc.z);
            atomicAdd(&sred[4 * l + 3], acc.w);
        }
        __syncthreads();
        if (threadIdx.x < 64)
            atomicAdd(&g_m[threadIdx.x], sred[threadIdx.x]);
        // last completed block applies the final projection
        __syncthreads();
        if (threadIdx.x == 0) {
            __threadfence();
            islast = (atomicAdd(&g_done, 1) == GB_AGG - 1);
        }
        __syncthreads();
        if (islast) {
            if (threadIdx.x == 0) g_done = 0;      // reset for next call
            if (threadIdx.x < 64) {
                int o = threadIdx.x;
                float s = 0.f;
#pragma unroll 8
                for (int k2 = 0; k2 < 64; k2++)
                    s += __ldg(&W2[o * 64 + k2]) * atomicAdd(&g_m[k2], 0.f);
                out[o] = s * (1.0f / N_NODES) + __ldg(&b2[o]);
            }
        }
    }
}

// ---------------- launch ----------------
extern "C" void kernel_launch(void* const* d_in, const int* in_sizes, int n_in,
                              void* d_out, int out_size) {
    const float* x   = (const float*)d_in[0];
    const int*   ei  = (const int*)d_in[1];
    // d_in[2] = edge_attr (unused; GATConv edge_dim=None)
    const float* W1  = (const float*)d_in[3];
    const float* as1 = (const float*)d_in[4];
    const float* ad1 = (const float*)d_in[5];
    const float* b1  = (const float*)d_in[6];
    const float* W2  = (const float*)d_in[7];
    const float* as2 = (const float*)d_in[8];
    const float* ad2 = (const float*)d_in[9];
    const float* b2  = (const float*)d_in[10];
    float* out = (float*)d_out;

    // (0) layer-1 tf32 mma gemm + dst histogram/rank capture (fused)
    k_gemm1<<<GB_G1 + GB_HIST, 256>>>(x, W1, as1, ad1, ei);
    // (1) rowptr via single-kernel decoupled lookback scan
    k_scan<<<NB_SCAN, 1024>>>();
    // (2) atomic-free adjacency fill (MLP 4) + u/v vectors + scratch reset
    k_fill<<<GB_FILL + 1, 512>>>(ei, W2, as2, ad2);
    // (3) layer-1 aggregation (also emits layer-2 logit halves)
    k_agg<<<GB_AGG, 512>>>(b1, nullptr, nullptr, nullptr, 1);
    // (4) layer-2 aggregation -> g_m; last block applies out = W2 (g_m/N) + b2
    k_agg<<<GB_AGG, 512>>>(nullptr, W2, b2, out, 2);
}

// round 16
// speedup vs baseline: 1.0509x; 1.0509x over previous
#include <cuda_runtime.h>
#include <cuda_fp16.h>

#define N_NODES 100000
#define N_EDGES 1600000
#define NB_SCAN 98              // ceil((N_NODES+1)/1024)
#define NEG_SLOPE 0.2f
#define FULLM 0xffffffffu
#define GB_G1 782               // ceil(N_NODES/128) gemm tiles
#define GB_HIST 3125            // ceil(N_EDGES/512): 2 edges per thread
#define HIST_HALF 800000

// ---------------- scratch (device globals; zero-initialized at module load) ----------
// Cross-call invariant: g_deg and g_tstat are zero at the start of every
// kernel_launch call — module-load zero-init covers the first call; k_fill
// re-zeroes them (after their last use) for every later call. g_m is zeroed
// by k_fill each call before agg2 accumulates into it.
__device__ int      g_deg[N_NODES + 1];
__device__ int      g_rowptr[N_NODES + 1];
__device__ int      g_ord[N_EDGES];       // within-dst-bucket rank of each edge
__device__ unsigned g_tstat[NB_SCAN];     // lookback status: [31:30] flag (1=agg,2=prefix), [29:0] value
__device__ int      g_adj[N_EDGES];       // src indices in CSR (dst-grouped) order
__device__ uint2    g_h[N_NODES * 16];    // layer-1 features, fp16 rows (64 x half = 128B/row)
__device__ uint2    g_feat[N_NODES * 16]; // layer-1 output, fp16 rows (layer-2 gather source)
__device__ float    g_as[N_NODES];        // layer-1 logit halves (fp32)
__device__ float    g_ad[N_NODES];
__device__ float    g_as2[N_NODES];       // layer-2 logit halves (feat . u / feat . v)
__device__ float    g_ad2[N_NODES];
__device__ float    g_u[64];              // u = W2^T a_src2
__device__ float    g_v[64];              // v = W2^T a_dst2
__device__ float    g_m[64];              // softmax-weighted feat aggregate (sum over nodes)

__device__ __forceinline__ uint2 pack4h(float a, float b, float c, float d) {
    __half2 p0 = __floats2half2_rn(a, b);
    __half2 p1 = __floats2half2_rn(c, d);
    uint2 r;
    r.x = *reinterpret_cast<unsigned*>(&p0);
    r.y = *reinterpret_cast<unsigned*>(&p1);
    return r;
}
__device__ __forceinline__ unsigned tf32b(float f) {
    unsigned r;
    asm("cvt.rna.tf32.f32 %0, %1;" : "=r"(r) : "f"(f));
    return r;
}
__device__ __forceinline__ unsigned packh2(float a, float b) {
    __half2 p = __floats2half2_rn(a, b);
    return *reinterpret_cast<unsigned*>(&p);
}
__device__ __forceinline__ __half2 u2h2(unsigned u) {
    return *reinterpret_cast<__half2*>(&u);
}

// ---------------- tf32 mma.sync GEMM (h = X @ W1^T) + attention logits ---------------
// Block = 256 threads = 8 warps; tile 128 nodes x 64 outs. Warp w owns rows
// w*16..+15; per warp 8 n-blocks of m16n8k8 tf32 mma (fp32 accumulate).
// K staged 16 at a time into smem (tf32-converted), row stride 20 words:
// all A/B fragment LDS patterns are bank-conflict-free. Logits reduced
// in-warp over the 4 quad threads. h written as fp16 rows (agg layout).
// HIST blocks (>= GB_G1) run the dst-degree histogram + bucket-rank capture,
// 2 coalesced edges per thread (MLP 2 on the ld->atomic chain); the atomicAdd
// return value IS the edge's rank -> k_fill needs no atomics.
__global__ void __launch_bounds__(256)
k_gemm1(const float* __restrict__ X,
        const float* __restrict__ W,
        const float* __restrict__ avsrc,
        const float* __restrict__ avdst,
        const int* __restrict__ ei) {
    if (blockIdx.x >= GB_G1) {
        int e = (blockIdx.x - GB_G1) * 256 + threadIdx.x;
#pragma unroll
        for (int i = 0; i < 2; i++, e += HIST_HALF) {
            if (e < N_EDGES) {
                int d = __ldg(&ei[N_EDGES + e]);
                g_ord[e] = atomicAdd(&g_deg[d + 1], 1);
            }
        }
        return;
    }
    __shared__ unsigned xs[128][20];   // X chunk, tf32 bits, [row][k0..15], stride 20
    __shared__ unsigned ws[64][20];    // W chunk, tf32 bits, [out][k0..15]

    const int tid  = threadIdx.x;
    const int lane = tid & 31;
    const int wid  = tid >> 5;         // warp 0..7
    const int g    = lane >> 2;        // groupID (row-in-16 / col-in-8)
    const int tg   = lane & 3;         // threadID_in_group
    const int nbase = blockIdx.x * 128;
    const int m0 = wid * 16;

    const float4* X4 = (const float4*)X;   // 32 float4 per 128-float row
    const float4* W4 = (const float4*)W;

    float acc[8][4];
#pragma unroll
    for (int nb = 0; nb < 8; nb++)
#pragma unroll
        for (int i = 0; i < 4; i++) acc[nb][i] = 0.f;

#pragma unroll 1
    for (int ch = 0; ch < 8; ch++) {
        __syncthreads();
        // stage X chunk: 128 rows x 16 k (512 float4, 2 per thread)
#pragma unroll
        for (int it = 0; it < 2; it++) {
            int idx = tid + it * 256;
            int r  = idx >> 2;
            int c4 = idx & 3;
            int xrow = min(nbase + r, N_NODES - 1);        // clamp tail (stores guarded)
            float4 v = __ldg(&X4[(long)xrow * 32 + ch * 4 + c4]);
            *(uint4*)&xs[r][c4 * 4] =
                make_uint4(tf32b(v.x), tf32b(v.y), tf32b(v.z), tf32b(v.w));
        }
        // stage W chunk: 64 rows x 16 k (256 float4, 1 per thread)
        {
            int r  = tid >> 2;
            int c4 = tid & 3;
            float4 v = __ldg(&W4[(long)r * 32 + ch * 4 + c4]);
            *(uint4*)&ws[r][c4 * 4] =
                make_uint4(tf32b(v.x), tf32b(v.y), tf32b(v.z), tf32b(v.w));
        }
        __syncthreads();

#pragma unroll
        for (int ks = 0; ks < 2; ks++) {
            const int kb = ks * 8;
            unsigned a0 = xs[m0 + g][kb + tg];
            unsigned a1 = xs[m0 + g + 8][kb + tg];
            unsigned a2 = xs[m0 + g][kb + tg + 4];
            unsigned a3 = xs[m0 + g + 8][kb + tg + 4];
#pragma unroll
            for (int nb = 0; nb < 8; nb++) {
                unsigned b0 = ws[nb * 8 + g][kb + tg];
                unsigned b1 = ws[nb * 8 + g][kb + tg + 4];
                asm volatile(
                    "mma.sync.aligned.m16n8k8.row.col.f32.tf32.tf32.f32 "
                    "{%0,%1,%2,%3}, {%4,%5,%6,%7}, {%8,%9}, {%0,%1,%2,%3};"
                    : "+f"(acc[nb][0]), "+f"(acc[nb][1]),
                      "+f"(acc[nb][2]), "+f"(acc[nb][3])
                    : "r"(a0), "r"(a1), "r"(a2), "r"(a3), "r"(b0), "r"(b1));
            }
        }
    }

    // epilogue: thread holds rows node0/node1, cols {nb*8 + tg*2, +1}
    const int node0 = nbase + m0 + g;
    const int node1 = node0 + 8;
    unsigned* H2 = (unsigned*)g_h;     // half2 words, 32 per node row

    float sp0 = 0.f, dp0 = 0.f, sp1 = 0.f, dp1 = 0.f;
    const float2* AS2 = (const float2*)avsrc;
    const float2* AD2 = (const float2*)avdst;
#pragma unroll
    for (int nb = 0; nb < 8; nb++) {
        float2 sv = __ldg(&AS2[nb * 4 + tg]);
        float2 dv = __ldg(&AD2[nb * 4 + tg]);
        sp0 += acc[nb][0] * sv.x + acc[nb][1] * sv.y;
        dp0 += acc[nb][0] * dv.x + acc[nb][1] * dv.y;
        sp1 += acc[nb][2] * sv.x + acc[nb][3] * sv.y;
        dp1 += acc[nb][2] * dv.x + acc[nb][3] * dv.y;
        if (node0 < N_NODES)
            H2[(long)node0 * 32 + nb * 4 + tg] = packh2(acc[nb][0], acc[nb][1]);
        if (node1 < N_NODES)
            H2[(long)node1 * 32 + nb * 4 + tg] = packh2(acc[nb][2], acc[nb][3]);
    }
    // reduce over the 4 quad threads sharing a row
#pragma unroll
    for (int m = 1; m < 4; m <<= 1) {
        sp0 += __shfl_xor_sync(FULLM, sp0, m);
        dp0 += __shfl_xor_sync(FULLM, dp0, m);
        sp1 += __shfl_xor_sync(FULLM, sp1, m);
        dp1 += __shfl_xor_sync(FULLM, dp1, m);
    }
    if (tg == 0) {
        if (node0 < N_NODES) { g_as[node0] = sp0; g_ad[node0] = dp0; }
        if (node1 < N_NODES) { g_as[node1] = sp1; g_ad[node1] = dp1; }
    }
}

// ---------------- single-kernel decoupled-lookback scan of g_deg -> g_rowptr ----------
__global__ void __launch_bounds__(1024) k_scan() {
    __shared__ int s[1024];
    __shared__ int s_prefix;
    const int t = threadIdx.x;
    const int tile = blockIdx.x;
    const int i = tile * 1024 + t;
    int v = (i <= N_NODES) ? g_deg[i] : 0;
    s[t] = v;
    __syncthreads();
    for (int off = 1; off < 1024; off <<= 1) {
        int x = (t >= off) ? s[t - off] : 0;
        __syncthreads();
        s[t] += x;
        __syncthreads();
    }
    const int inc = s[t];
    const int total = s[1023];

    if (t == 0) {
        if (tile == 0) {
            atomicExch(&g_tstat[0], (2u << 30) | (unsigned)total);
            s_prefix = 0;
        } else {
            atomicExch(&g_tstat[tile], (1u << 30) | (unsigned)total);
            int prefix = 0;
            int p = tile - 1;
            while (true) {
                unsigned st = *(volatile unsigned*)&g_tstat[p];
                unsigned f = st >> 30;
                if (f == 0u) continue;
                prefix += (int)(st & 0x3FFFFFFFu);
                if (f == 2u) break;
                p--;
            }
            atomicExch(&g_tstat[tile], (2u << 30) | (unsigned)(prefix + total));
            s_prefix = prefix;
        }
    }
    __syncthreads();
    const int val = inc + s_prefix;
    if (i <= N_NODES) g_rowptr[i] = val;
}

// ---------------- atomic-free adjacency fill + u/v precompute + cleanup -------------
// pos = rowptr[dst] + precomputed bucket rank: loads + one scattered store only
// (scatter-sector bound; MLP restructure measured as a regression — keep 1/thread).
// Block 3125 computes u = W2^T a_src2, v = W2^T a_dst2 and zeroes g_m.
__global__ void __launch_bounds__(512) k_fill(const int* __restrict__ ei,
                                              const float* __restrict__ W2,
                                              const float* __restrict__ as2v,
                                              const float* __restrict__ ad2v) {
    if (blockIdx.x == 3125) {
        int k = threadIdx.x;
        if (k < 64) {
            float u = 0.f, v = 0.f;
#pragma unroll 8
            for (int o = 0; o < 64; o++) {
                float w = __ldg(&W2[o * 64 + k]);
                u += __ldg(&as2v[o]) * w;
                v += __ldg(&ad2v[o]) * w;
            }
            g_u[k] = u;
            g_v[k] = v;
            g_m[k] = 0.f;
        }
        return;
    }
    int gid = blockIdx.x * 512 + threadIdx.x;
    if (gid <= N_NODES) g_deg[gid] = 0;       // reset for next kernel_launch call
    if (gid < NB_SCAN) g_tstat[gid] = 0u;     // reset lookback status
    if (gid < N_EDGES) {
        int d   = __ldg(&ei[N_EDGES + gid]);
        int pos = __ldg(&g_rowptr[d]) + __ldg(&g_ord[gid]);
        g_adj[pos] = __ldg(&ei[gid]);
    }
}

// ---------------- half-warp-per-node softmax aggregation (atomic-free) ---------------
// 16 lanes own one node; lane l holds features [4l, 4l+4) as fp16 (8B/lane):
// one 128B wavefront per gathered edge row. Accumulation in fp16 via HFMA2 —
// the per-chunk edge weight is converted once per lane to a broadcast half2
// (scaled by 1/16, exact in fp16, restored x16 in fp32 after the loop;
// overflow would need sum(ex*|h|) > 1e6, an ~8-sigma event for N(0,2) logits)
// and shfl'd as raw bits. dsum, softmax normalize, logits, bias all stay
// fp32. Single predicated 4-wide batch loop: invalid tail slots carry
// (s=0, exh=0) so they gather row 0 with zero weight.
// mode 1: bias+relu, store g_feat (fp16) + emit layer-2 logit halves
//         as2 = feat.u, ad2 = feat.v (replaces the layer-2 gemm by linearity).
// mode 2: pool normalized aggregate into g_m (k_fin applies W2, 1/N, b2).
__global__ void __launch_bounds__(512)
k_agg(const float* __restrict__ b, int mode) {
    __shared__ float sred[64];
    if (mode == 2) {
        if (threadIdx.x < 64) sred[threadIdx.x] = 0.f;
        __syncthreads();
    }
    const int lane = threadIdx.x & 31;
    const int l = lane & 15;
    const unsigned hm = 0xFFFFu << (lane & 16);
    const int node = (blockIdx.x * 512 + threadIdx.x) >> 4;   // exact: 3125*512/16 = 100000

    const uint2* H = (mode == 1) ? g_h : g_feat;
    const float* asp = (mode == 1) ? g_as : g_as2;
    const float* adp = (mode == 1) ? g_ad : g_ad2;

    const float adn = adp[node];
    float e0 = asp[node] + adn;
    e0 = (e0 > 0.f) ? e0 : NEG_SLOPE * e0;
    const float exs = __expf(e0);                 // self-loop term (fp32 for denom)

    uint2 hrow = __ldg(H + (long)node * 16 + l);
    __half2 es2 = __float2half2_rn(exs * 0.0625f);
    __half2 hacc0 = __hmul2(es2, u2h2(hrow.x));
    __half2 hacc1 = __hmul2(es2, u2h2(hrow.y));
    float dsum = 0.f;

    const int beg = __ldg(&g_rowptr[node]);
    const int end = __ldg(&g_rowptr[node + 1]);
    for (int k = beg; k < end; k += 16) {
        int idx = k + l;
        int s = 0;
        unsigned exh = 0u;                        // half2(0,0)
        if (idx < end) {
            s = __ldg(&g_adj[idx]);
            float e = __ldg(&asp[s]) + adn;
            e = (e > 0.f) ? e : NEG_SLOPE * e;
            float ex = __expf(e);
            dsum += ex;
            __half2 t = __float2half2_rn(ex * 0.0625f);
            exh = *reinterpret_cast<unsigned*>(&t);
        }
        const int cnt = min(16, end - k);
        for (int j = 0; j < cnt; j += 4) {
            int      s0 = __shfl_sync(hm, s, j, 16);
            int      s1 = __shfl_sync(hm, s, j + 1, 16);
            int      s2 = __shfl_sync(hm, s, j + 2, 16);
            int      s3 = __shfl_sync(hm, s, j + 3, 16);
            unsigned e0b = __shfl_sync(hm, exh, j, 16);
            unsigned e1b = __shfl_sync(hm, exh, j + 1, 16);
            unsigned e2b = __shfl_sync(hm, exh, j + 2, 16);
            unsigned e3b = __shfl_sync(hm, exh, j + 3, 16);
            uint2 h0 = __ldg(H + (long)s0 * 16 + l);
            uint2 h1 = __ldg(H + (long)s1 * 16 + l);
            uint2 h2 = __ldg(H + (long)s2 * 16 + l);
            uint2 h3 = __ldg(H + (long)s3 * 16 + l);
            hacc0 = __hfma2(u2h2(e0b), u2h2(h0.x), hacc0);
            hacc1 = __hfma2(u2h2(e0b), u2h2(h0.y), hacc1);
            hacc0 = __hfma2(u2h2(e1b), u2h2(h1.x), hacc0);
            hacc1 = __hfma2(u2h2(e1b), u2h2(h1.y), hacc1);
            hacc0 = __hfma2(u2h2(e2b), u2h2(h2.x), hacc0);
            hacc1 = __hfma2(u2h2(e2b), u2h2(h2.y), hacc1);
            hacc0 = __hfma2(u2h2(e3b), u2h2(h3.x), hacc0);
            hacc1 = __hfma2(u2h2(e3b), u2h2(h3.y), hacc1);
        }
    }
#pragma unroll
    for (int m = 8; m; m >>= 1) dsum += __shfl_xor_sync(hm, dsum, m, 16);

    // restore scale (x16) and normalize in fp32
    float2 f0 = __half22float2(hacc0);
    float2 f1 = __half22float2(hacc1);
    const float inv = 16.0f / (dsum + exs);
    float4 acc = make_float4(f0.x * inv, f0.y * inv, f1.x * inv, f1.y * inv);

    if (mode == 1) {
        float4 bb = __ldg((const float4*)b + l);
        float4 r = make_float4(fmaxf(acc.x + bb.x, 0.f),
                               fmaxf(acc.y + bb.y, 0.f),
                               fmaxf(acc.z + bb.z, 0.f),
                               fmaxf(acc.w + bb.w, 0.f));
        g_feat[(long)node * 16 + l] = pack4h(r.x, r.y, r.z, r.w);
        // layer-2 logit halves from the in-register (fp32) feat row
        float4 uu = __ldg((const float4*)g_u + l);
        float4 vv = __ldg((const float4*)g_v + l);
        float sp = r.x * uu.x + r.y * uu.y + r.z * uu.z + r.w * uu.w;
        float dp = r.x * vv.x + r.y * vv.y + r.z * vv.z + r.w * vv.w;
#pragma unroll
        for (int m = 8; m; m >>= 1) {
            sp += __shfl_xor_sync(hm, sp, m, 16);
            dp += __shfl_xor_sync(hm, dp, m, 16);
        }
        if (l == 0) { g_as2[node] = sp; g_ad2[node] = dp; }
    } else {
        // pool normalized aggregate (W2/b2/(1/N) applied in k_fin)
        __syncwarp(FULLM);
        acc.x += __shfl_xor_sync(FULLM, acc.x, 16);
        acc.y += __shfl_xor_sync(FULLM, acc.y, 16);
        acc.z += __shfl_xor_sync(FULLM, acc.z, 16);
        acc.w += __shfl_xor_sync(FULLM, acc.w, 16);
        if (lane < 16) {
            atomicAdd(&sred[4 * l + 0], acc.x);
            atomicAdd(&sred[4 * l + 1], acc.y);
            atomicAdd(&sred[4 * l + 2], acc.z);
            atomicAdd(&sred[4 * l + 3], acc.w);
        }
        __syncthreads();
        if (threadIdx.x < 64)
            atomicAdd(&g_m[threadIdx.x], sred[threadIdx.x]);
    }
}

// ---------------- final projection: out = W2 (g_m / N) + b2 ----------------
__global__ void k_fin(const float* __restrict__ W2,
                      const float* __restrict__ b2,
                      float* __restrict__ out) {
    int o = threadIdx.x;
    float s = 0.f;
#pragma unroll 8
    for (int k = 0; k < 64; k++)
        s += __ldg(&W2[o * 64 + k]) * g_m[k];
    out[o] = s * (1.0f / N_NODES) + __ldg(&b2[o]);
}

// ---------------- launch ----------------
extern "C" void kernel_launch(void* const* d_in, const int* in_sizes, int n_in,
                              void* d_out, int out_size) {
    const float* x   = (const float*)d_in[0];
    const int*   ei  = (const int*)d_in[1];
    // d_in[2] = edge_attr (unused; GATConv edge_dim=None)
    const float* W1  = (const float*)d_in[3];
    const float* as1 = (const float*)d_in[4];
    const float* ad1 = (const float*)d_in[5];
    const float* b1  = (const float*)d_in[6];
    const float* W2  = (const float*)d_in[7];
    const float* as2 = (const float*)d_in[8];
    const float* ad2 = (const float*)d_in[9];
    const float* b2  = (const float*)d_in[10];
    float* out = (float*)d_out;

    // (0) layer-1 tf32 mma gemm + dst histogram/rank capture (fused)
    k_gemm1<<<GB_G1 + GB_HIST, 256>>>(x, W1, as1, ad1, ei);
    // (1) rowptr via single-kernel decoupled lookback scan
    k_scan<<<NB_SCAN, 1024>>>();
    // (2) atomic-free adjacency fill + u/v vectors + scratch reset
    k_fill<<<3126, 512>>>(ei, W2, as2, ad2);
    // (3) layer-1 aggregation (also emits layer-2 logit halves)
    k_agg<<<3125, 512>>>(b1, 1);
    // (4) layer-2 aggregation -> pooled mean vector g_m
    k_agg<<<3125, 512>>>(nullptr, 2);
    // (5) out = W2 (g_m/N) + b2
    k_fin<<<1, 64>>>(W2, b2, out);
}